// round 13
// baseline (speedup 1.0000x reference)
#include <cuda_runtime.h>

#define N_NODES 100000
#define E_MSG   3200000
#define E_SC    1000000
#define IN_DIM  12
#define HID     64
#define EMB     32
#define EDGE_F  10
#define EDGE_REPR 74
#define D2PAD   80   // dec_W2 row padded to 2x40 halves

// ---------------- scratch (static device globals; zero-init at load) ---------
// g_agg1 is re-zeroed by sage1 after consumption; g_cnt and g_agg2p are
// re-zeroed by sage2 after consumption. Graph replays always see zeros.
__device__ float g_agg1 [N_NODES * IN_DIM];
__device__ float g_cnt  [N_NODES];
__device__ float g_h    [N_NODES * HID];
__device__ float g_p    [N_NODES * EMB];   // h @ Wn2 (projected, 32-dim)
__device__ float g_agg2p[N_NODES * EMB];   // scatter of g_p
__device__ float g_emb  [N_NODES * EMB];

// ---------------- int32/int64 index handling ---------------------------------
__device__ __forceinline__ bool idx_is64(const void* p) {
    const int* q = (const int*)p;
    return (q[1] | q[3] | q[5]) == 0;
}
__device__ __forceinline__ long long ld_idx(const void* p, long long i, bool is64) {
    if (is64) return ((const long long*)p)[i];
    return (long long)((const int*)p)[i];
}

__device__ __forceinline__ float warp_sum(float v) {
#pragma unroll
    for (int o = 16; o > 0; o >>= 1) v += __shfl_xor_sync(0xffffffffu, v, o);
    return v;
}

// ---------------- packed f32x2 helpers (sm_100+) ------------------------------
__device__ __forceinline__ unsigned long long pk2(float a, float b) {
    unsigned long long r;
    asm("mov.b64 %0, {%1,%2};" : "=l"(r) : "f"(a), "f"(b));
    return r;
}
__device__ __forceinline__ void upk2(unsigned long long p, float& a, float& b) {
    asm("mov.b64 {%0,%1}, %2;" : "=f"(a), "=f"(b) : "l"(p));
}
__device__ __forceinline__ void fma2(unsigned long long& d,
                                     unsigned long long a, unsigned long long b) {
    asm("fma.rn.f32x2 %0, %1, %2, %0;" : "+l"(d) : "l"(a), "l"(b));
}

// ---------------- vector float atomic (sm_90+) --------------------------------
__device__ __forceinline__ void red_add_v4(float* addr, float4 v) {
    asm volatile("red.global.add.v4.f32 [%0], {%1,%2,%3,%4};"
                 :: "l"(addr), "f"(v.x), "f"(v.y), "f"(v.z), "f"(v.w) : "memory");
}

// ---------------- scatter layer-1 features + degree counts -------------------
__global__ __launch_bounds__(256) void scatter1_kernel(const void* __restrict__ ei,
                                                       const float* __restrict__ nf) {
    int e = blockIdx.x * 256 + threadIdx.x;
    if (e >= E_MSG) return;
    bool is64 = idx_is64(ei);
    long long s = ld_idx(ei, e, is64);
    long long d = ld_idx(ei, (long long)E_MSG + e, is64);
    const float4* x = (const float4*)(nf + s * IN_DIM);   // 48B rows, 16B aligned
    float* a = g_agg1 + d * IN_DIM;
#pragma unroll
    for (int j = 0; j < 3; j++) red_add_v4(a + 4 * j, x[j]);
    atomicAdd(g_cnt + d, 1.f);
}

// ---------------- SAGE layer 1: 12 -> 64 + LN + relu, fused proj h@Wn2 -------
__global__ __launch_bounds__(256) void sage1_kernel(const float* __restrict__ nf,
                                                    const float* __restrict__ Ws,
                                                    const float* __restrict__ Wn,
                                                    const float* __restrict__ b,
                                                    const float* __restrict__ g,
                                                    const float* __restrict__ be,
                                                    const float* __restrict__ Wn2) {
    __shared__ float sWs[IN_DIM * HID], sWn[IN_DIM * HID], sW2[HID * EMB];
    __shared__ float sb[HID], sg[HID], sbe[HID];
    for (int i = threadIdx.x; i < IN_DIM * HID; i += 256) { sWs[i] = Ws[i]; sWn[i] = Wn[i]; }
    for (int i = threadIdx.x; i < HID * EMB; i += 256) sW2[i] = Wn2[i];
    if (threadIdx.x < HID) {
        sb[threadIdx.x] = b[threadIdx.x];
        sg[threadIdx.x] = g[threadIdx.x];
        sbe[threadIdx.x] = be[threadIdx.x];
    }
    __syncthreads();
    int n = blockIdx.x * 8 + (threadIdx.x >> 5);
    int lane = threadIdx.x & 31;
    float inv = 1.f / fmaxf(g_cnt[n], 1.f);
    float h0 = sb[lane], h1 = sb[lane + 32];
#pragma unroll
    for (int k = 0; k < IN_DIM; k++) {
        float xk = nf[n * IN_DIM + k];
        float ak = g_agg1[n * IN_DIM + k] * inv;
        h0 += xk * sWs[k * HID + lane]      + ak * sWn[k * HID + lane];
        h1 += xk * sWs[k * HID + lane + 32] + ak * sWn[k * HID + lane + 32];
    }
    // self-clean agg1 ONLY (g_cnt is still needed by sage2; sage2 zeroes it)
    __syncwarp();
    if (lane < IN_DIM) g_agg1[n * IN_DIM + lane] = 0.f;

    float s1 = warp_sum(h0 + h1);
    float s2 = warp_sum(h0 * h0 + h1 * h1);
    float mu  = s1 * (1.f / 64.f);
    float var = s2 * (1.f / 64.f) - mu * mu;
    float r = rsqrtf(var + 1e-5f);
    float o0 = fmaxf((h0 - mu) * r * sg[lane]      + sbe[lane],      0.f);
    float o1 = fmaxf((h1 - mu) * r * sg[lane + 32] + sbe[lane + 32], 0.f);
    g_h[n * HID + lane]      = o0;
    g_h[n * HID + lane + 32] = o1;
    // fused projection: p = h @ Wn2 (h is lane-distributed in o0/o1)
    float acc = 0.f;
#pragma unroll
    for (int k = 0; k < 32; k++)
        acc += __shfl_sync(0xffffffffu, o0, k) * sW2[k * EMB + lane];
#pragma unroll
    for (int k = 0; k < 32; k++)
        acc += __shfl_sync(0xffffffffu, o1, k) * sW2[(k + 32) * EMB + lane];
    g_p[n * EMB + lane] = acc;
}

// ---------------- scatter layer-2 (projected): p[src] -> agg2p[dst] ----------
__global__ __launch_bounds__(256) void scatter2_kernel(const void* __restrict__ ei) {
    int e = blockIdx.x * 256 + threadIdx.x;
    if (e >= E_MSG) return;
    bool is64 = idx_is64(ei);
    long long s = ld_idx(ei, e, is64);
    long long d = ld_idx(ei, (long long)E_MSG + e, is64);
    const float4* ps = (const float4*)(g_p + s * EMB);    // 128B rows
    float* pd = g_agg2p + d * EMB;
#pragma unroll
    for (int j = 0; j < 8; j++) red_add_v4(pd + 4 * j, ps[j]);
}

// ---------------- SAGE layer 2: 64 -> 32 + LN + relu -------------------------
__global__ __launch_bounds__(256) void sage2_kernel(const float* __restrict__ Ws,
                                                    const float* __restrict__ b,
                                                    const float* __restrict__ g,
                                                    const float* __restrict__ be) {
    __shared__ float sWs[HID * EMB];
    __shared__ float sb[EMB], sg[EMB], sbe[EMB];
    for (int i = threadIdx.x; i < HID * EMB; i += 256) sWs[i] = Ws[i];
    if (threadIdx.x < EMB) {
        sb[threadIdx.x] = b[threadIdx.x];
        sg[threadIdx.x] = g[threadIdx.x];
        sbe[threadIdx.x] = be[threadIdx.x];
    }
    __syncthreads();
    int n = blockIdx.x * 8 + (threadIdx.x >> 5);
    int lane = threadIdx.x & 31;
    float inv = 1.f / fmaxf(g_cnt[n], 1.f);
    float hl = g_h[n * HID + lane];
    float hh = g_h[n * HID + 32 + lane];
    float acc = sb[lane] + g_agg2p[n * EMB + lane] * inv;
    // self-clean agg2p (each lane rewrites the element it just read) and cnt
    g_agg2p[n * EMB + lane] = 0.f;
    if (lane == 0) g_cnt[n] = 0.f;
#pragma unroll
    for (int k = 0; k < 32; k++)
        acc += __shfl_sync(0xffffffffu, hl, k) * sWs[k * EMB + lane];
#pragma unroll
    for (int k = 0; k < 32; k++)
        acc += __shfl_sync(0xffffffffu, hh, k) * sWs[(k + 32) * EMB + lane];
    float s1 = warp_sum(acc);
    float s2 = warp_sum(acc * acc);
    float mu  = s1 * (1.f / 32.f);
    float var = s2 * (1.f / 32.f) - mu * mu;
    float r = rsqrtf(var + 1e-5f);
    g_emb[n * EMB + lane] = fmaxf((acc - mu) * r * sg[lane] + sbe[lane], 0.f);
}

// ---------------- fused edge_rep + edge MLP (packed f32x2, streaming enc1) ---
// Shared layout (floats): W1(74*64) W2(64*32) D1(32*64) D2(64*80) b1(64) b2(32) b3(64) b4(80)
#define SM_W1 0
#define SM_W2 (SM_W1 + EDGE_REPR * HID)
#define SM_D1 (SM_W2 + HID * EMB)
#define SM_D2 (SM_D1 + EMB * HID)
#define SM_B1 (SM_D2 + HID * D2PAD)
#define SM_B2 (SM_B1 + HID)
#define SM_B3 (SM_B2 + EMB)
#define SM_B4 (SM_B3 + HID)
#define SM_TOTAL (SM_B4 + D2PAD)   // 14192 floats = 56768 B

#define MLP_THREADS 128

// sweep one broadcast multiplier pair m against a 64-wide weight row into acc[32]
#define SWEEP64(acc, m, rowptr)                                            \
    {                                                                      \
        const ulonglong2* _w = (const ulonglong2*)(rowptr);                \
        _Pragma("unroll")                                                  \
        for (int _jj = 0; _jj < 16; _jj++) {                               \
            ulonglong2 _t = _w[_jj];                                       \
            fma2((acc)[2 * _jj], (m), _t.x);                               \
            fma2((acc)[2 * _jj + 1], (m), _t.y);                           \
        }                                                                  \
    }

__global__ __launch_bounds__(MLP_THREADS, 3) void edge_mlp_kernel(
    const void* __restrict__ srcn, const void* __restrict__ dstn,
    const float* __restrict__ ea,
    const float* __restrict__ eW1, const float* __restrict__ eb1,
    const float* __restrict__ eW2, const float* __restrict__ eb2,
    const float* __restrict__ dW1, const float* __restrict__ db1,
    const float* __restrict__ dW2, const float* __restrict__ db2,
    float* __restrict__ out_recon, float* __restrict__ out_er) {
    extern __shared__ float sm[];
    for (int i = threadIdx.x; i < EDGE_REPR * HID; i += MLP_THREADS) sm[SM_W1 + i] = eW1[i];
    for (int i = threadIdx.x; i < HID * EMB; i += MLP_THREADS)       sm[SM_W2 + i] = eW2[i];
    for (int i = threadIdx.x; i < EMB * HID; i += MLP_THREADS)       sm[SM_D1 + i] = dW1[i];
    for (int i = threadIdx.x; i < HID * D2PAD; i += MLP_THREADS) {
        int k = i / D2PAD, j = i - k * D2PAD;
        sm[SM_D2 + i] = (j < EDGE_REPR) ? dW2[k * EDGE_REPR + j] : 0.f;
    }
    for (int i = threadIdx.x; i < HID; i += MLP_THREADS) { sm[SM_B1 + i] = eb1[i]; sm[SM_B3 + i] = db1[i]; }
    for (int i = threadIdx.x; i < EMB; i += MLP_THREADS)   sm[SM_B2 + i] = eb2[i];
    for (int i = threadIdx.x; i < D2PAD; i += MLP_THREADS) sm[SM_B4 + i] = (i < EDGE_REPR) ? db2[i] : 0.f;
    __syncthreads();

    int e = blockIdx.x * MLP_THREADS + threadIdx.x;
    if (e >= E_SC) return;
    bool is64s = idx_is64(srcn);
    bool is64d = idx_is64(dstn);
    long long s = ld_idx(srcn, e, is64s);
    long long d = ld_idx(dstn, e, is64d);

    unsigned long long* o_er = (unsigned long long*)(out_er + (long long)e * EDGE_REPR);

    // -------- enc1 (streaming): a1 = er @ W1 + b1; er chunks also written out
    unsigned long long a1[HID / 2];
    {
        const unsigned long long* bp = (const unsigned long long*)(sm + SM_B1);
#pragma unroll
        for (int j = 0; j < HID / 2; j++) a1[j] = bp[j];
    }
    {
        const float4* es = (const float4*)(g_emb + s * EMB);
#pragma unroll
        for (int c = 0; c < 8; c++) {
            float4 v = es[c];
            o_er[2 * c]     = pk2(v.x, v.y);
            o_er[2 * c + 1] = pk2(v.z, v.w);
            int k = 4 * c;
            SWEEP64(a1, pk2(v.x, v.x), sm + SM_W1 + (k + 0) * HID);
            SWEEP64(a1, pk2(v.y, v.y), sm + SM_W1 + (k + 1) * HID);
            SWEEP64(a1, pk2(v.z, v.z), sm + SM_W1 + (k + 2) * HID);
            SWEEP64(a1, pk2(v.w, v.w), sm + SM_W1 + (k + 3) * HID);
        }
        const float4* ed = (const float4*)(g_emb + d * EMB);
#pragma unroll
        for (int c = 0; c < 8; c++) {
            float4 v = ed[c];
            o_er[16 + 2 * c]     = pk2(v.x, v.y);
            o_er[16 + 2 * c + 1] = pk2(v.z, v.w);
            int k = EMB + 4 * c;
            SWEEP64(a1, pk2(v.x, v.x), sm + SM_W1 + (k + 0) * HID);
            SWEEP64(a1, pk2(v.y, v.y), sm + SM_W1 + (k + 1) * HID);
            SWEEP64(a1, pk2(v.z, v.z), sm + SM_W1 + (k + 2) * HID);
            SWEEP64(a1, pk2(v.w, v.w), sm + SM_W1 + (k + 3) * HID);
        }
#pragma unroll
        for (int c = 0; c < EDGE_F / 2; c++) {
            float f0 = ea[(long long)e * EDGE_F + 2 * c];
            float f1 = ea[(long long)e * EDGE_F + 2 * c + 1];
            o_er[32 + c] = pk2(f0, f1);
            int k = 2 * EMB + 2 * c;
            SWEEP64(a1, pk2(f0, f0), sm + SM_W1 + (k + 0) * HID);
            SWEEP64(a1, pk2(f1, f1), sm + SM_W1 + (k + 1) * HID);
        }
    }

    // -------- enc2: 64 -> 32, relu applied to a1 on the fly --------
    unsigned long long a2[EMB / 2];
    {
        const unsigned long long* bp = (const unsigned long long*)(sm + SM_B2);
#pragma unroll
        for (int j = 0; j < EMB / 2; j++) a2[j] = bp[j];
#pragma unroll
        for (int kp = 0; kp < HID / 2; kp++) {
            float f0, f1;
            upk2(a1[kp], f0, f1);
            f0 = fmaxf(f0, 0.f);
            f1 = fmaxf(f1, 0.f);
            unsigned long long m0 = pk2(f0, f0);
            unsigned long long m1 = pk2(f1, f1);
            const ulonglong2* w0 = (const ulonglong2*)(sm + SM_W2 + (2 * kp) * EMB);
            const ulonglong2* w1 = (const ulonglong2*)(sm + SM_W2 + (2 * kp + 1) * EMB);
#pragma unroll
            for (int jj = 0; jj < 8; jj++) {
                ulonglong2 t0 = w0[jj];
                fma2(a2[2 * jj], m0, t0.x);
                fma2(a2[2 * jj + 1], m0, t0.y);
            }
#pragma unroll
            for (int jj = 0; jj < 8; jj++) {
                ulonglong2 t1 = w1[jj];
                fma2(a2[2 * jj], m1, t1.x);
                fma2(a2[2 * jj + 1], m1, t1.y);
            }
        }
    }

    // -------- dec1: 32 -> 64 (relu on a2 on the fly), result in a3 --------
    unsigned long long a3[HID / 2];
    {
        const unsigned long long* bp = (const unsigned long long*)(sm + SM_B3);
#pragma unroll
        for (int j = 0; j < HID / 2; j++) a3[j] = bp[j];
#pragma unroll
        for (int kp = 0; kp < EMB / 2; kp++) {
            float f0, f1;
            upk2(a2[kp], f0, f1);
            f0 = fmaxf(f0, 0.f);
            f1 = fmaxf(f1, 0.f);
            SWEEP64(a3, pk2(f0, f0), sm + SM_D1 + (2 * kp) * HID);
            SWEEP64(a3, pk2(f1, f1), sm + SM_D1 + (2 * kp + 1) * HID);
        }
    }
    // relu a3 in place (h2)
#pragma unroll
    for (int j = 0; j < HID / 2; j++) {
        float f0, f1;
        upk2(a3[j], f0, f1);
        a3[j] = pk2(fmaxf(f0, 0.f), fmaxf(f1, 0.f));
    }

    // -------- dec2: 64 -> 74 in two 40-column halves --------
    unsigned long long* o = (unsigned long long*)(out_recon + (long long)e * EDGE_REPR);
#pragma unroll
    for (int h = 0; h < 2; h++) {
        unsigned long long a4[20];
        const unsigned long long* bp = (const unsigned long long*)(sm + SM_B4 + h * 40);
#pragma unroll
        for (int j = 0; j < 20; j++) a4[j] = bp[j];
#pragma unroll
        for (int kp = 0; kp < HID / 2; kp++) {
            float f0, f1;
            upk2(a3[kp], f0, f1);
            unsigned long long m0 = pk2(f0, f0);
            unsigned long long m1 = pk2(f1, f1);
            const ulonglong2* w0 = (const ulonglong2*)(sm + SM_D2 + (2 * kp) * D2PAD + h * 40);
            const ulonglong2* w1 = (const ulonglong2*)(sm + SM_D2 + (2 * kp + 1) * D2PAD + h * 40);
#pragma unroll
            for (int jj = 0; jj < 10; jj++) {
                ulonglong2 t0 = w0[jj];
                fma2(a4[2 * jj], m0, t0.x);
                fma2(a4[2 * jj + 1], m0, t0.y);
            }
#pragma unroll
            for (int jj = 0; jj < 10; jj++) {
                ulonglong2 t1 = w1[jj];
                fma2(a4[2 * jj], m1, t1.x);
                fma2(a4[2 * jj + 1], m1, t1.y);
            }
        }
        if (h == 0) {
#pragma unroll
            for (int j = 0; j < 20; j++) o[j] = a4[j];        // cols 0..39
        } else {
#pragma unroll
            for (int j = 0; j < 17; j++) o[20 + j] = a4[j];   // cols 40..73
        }
    }
}

// ---------------- launcher ----------------------------------------------------
extern "C" void kernel_launch(void* const* d_in, const int* in_sizes, int n_in,
                              void* d_out, int out_size) {
    const float* nf   = (const float*)d_in[0];
    const void*  ei   = d_in[1];
    const float* ea   = (const float*)d_in[2];
    const void*  srcn = d_in[3];
    const void*  dstn = d_in[4];
    const float* Ws1 = (const float*)d_in[5];
    const float* Wn1 = (const float*)d_in[6];
    const float* b1  = (const float*)d_in[7];
    const float* g1  = (const float*)d_in[8];
    const float* be1 = (const float*)d_in[9];
    const float* Ws2 = (const float*)d_in[10];
    const float* Wn2 = (const float*)d_in[11];
    const float* b2  = (const float*)d_in[12];
    const float* g2  = (const float*)d_in[13];
    const float* be2 = (const float*)d_in[14];
    const float* eW1 = (const float*)d_in[15];
    const float* eb1 = (const float*)d_in[16];
    const float* eW2 = (const float*)d_in[17];
    const float* eb2 = (const float*)d_in[18];
    const float* dW1 = (const float*)d_in[19];
    const float* db1 = (const float*)d_in[20];
    const float* dW2 = (const float*)d_in[21];
    const float* db2 = (const float*)d_in[22];

    float* out_recon = (float*)d_out;                                   // [1M, 74]
    float* out_er    = (float*)d_out + (long long)E_SC * EDGE_REPR;     // [1M, 74]

    const int smem_mlp = SM_TOTAL * sizeof(float);  // 56768 B
    cudaFuncSetAttribute(edge_mlp_kernel, cudaFuncAttributeMaxDynamicSharedMemorySize, smem_mlp);

    scatter1_kernel<<<(E_MSG + 255) / 256, 256>>>(ei, nf);
    sage1_kernel<<<N_NODES / 8, 256>>>(nf, Ws1, Wn1, b1, g1, be1, Wn2);
    scatter2_kernel<<<(E_MSG + 255) / 256, 256>>>(ei);
    sage2_kernel<<<N_NODES / 8, 256>>>(Ws2, b2, g2, be2);
    edge_mlp_kernel<<<(E_SC + MLP_THREADS - 1) / MLP_THREADS, MLP_THREADS, smem_mlp>>>(
        srcn, dstn, ea, eW1, eb1, eW2, eb2, dW1, db1, dW2, db2, out_recon, out_er);
}

// round 14
// speedup vs baseline: 1.4902x; 1.4902x over previous
#include <cuda_runtime.h>

#define N_NODES 100000
#define E_MSG   3200000
#define E_SC    1000000
#define IN_DIM  12
#define HID     64
#define EMB     32
#define EDGE_F  10
#define EDGE_REPR 74
#define D2PAD   76   // dec_W2 row padded to multiple of 4

// ---------------- scratch (static device globals; zero-init at load) ---------
// Self-cleaning: sage1 re-zeroes g_agg1 after consuming; sage2 re-zeroes
// g_agg2p and g_cnt after consuming. Every graph replay sees zeroed buffers.
__device__ float g_agg1 [N_NODES * IN_DIM];
__device__ float g_cnt  [N_NODES];
__device__ float g_h    [N_NODES * HID];
__device__ float g_p    [N_NODES * EMB];   // h @ Wn2 (projected, 32-dim)
__device__ float g_agg2p[N_NODES * EMB];   // scatter of g_p
__device__ float g_emb  [N_NODES * EMB];

// ---------------- int32/int64 index handling ---------------------------------
__device__ __forceinline__ bool idx_is64(const void* p) {
    const int* q = (const int*)p;
    return (q[1] | q[3] | q[5]) == 0;
}
__device__ __forceinline__ long long ld_idx(const void* p, long long i, bool is64) {
    if (is64) return ((const long long*)p)[i];
    return (long long)((const int*)p)[i];
}

__device__ __forceinline__ float warp_sum(float v) {
#pragma unroll
    for (int o = 16; o > 0; o >>= 1) v += __shfl_xor_sync(0xffffffffu, v, o);
    return v;
}

// ---------------- packed f32x2 helpers (sm_100+) ------------------------------
__device__ __forceinline__ unsigned long long pk2(float a, float b) {
    unsigned long long r;
    asm("mov.b64 %0, {%1,%2};" : "=l"(r) : "f"(a), "f"(b));
    return r;
}
__device__ __forceinline__ void upk2(unsigned long long p, float& a, float& b) {
    asm("mov.b64 {%0,%1}, %2;" : "=f"(a), "=f"(b) : "l"(p));
}
__device__ __forceinline__ void fma2(unsigned long long& d,
                                     unsigned long long a, unsigned long long b) {
    asm("fma.rn.f32x2 %0, %1, %2, %0;" : "+l"(d) : "l"(a), "l"(b));
}

// ---------------- vector float atomic (sm_90+) --------------------------------
__device__ __forceinline__ void red_add_v4(float* addr, float4 v) {
    asm volatile("red.global.add.v4.f32 [%0], {%1,%2,%3,%4};"
                 :: "l"(addr), "f"(v.x), "f"(v.y), "f"(v.z), "f"(v.w) : "memory");
}

// ---------------- scatter layer-1 features + degree counts -------------------
__global__ __launch_bounds__(256) void scatter1_kernel(const void* __restrict__ ei,
                                                       const float* __restrict__ nf) {
    int e = blockIdx.x * 256 + threadIdx.x;
    if (e >= E_MSG) return;
    bool is64 = idx_is64(ei);
    long long s = ld_idx(ei, e, is64);
    long long d = ld_idx(ei, (long long)E_MSG + e, is64);
    const float4* x = (const float4*)(nf + s * IN_DIM);   // 48B rows, 16B aligned
    float* a = g_agg1 + d * IN_DIM;
#pragma unroll
    for (int j = 0; j < 3; j++) red_add_v4(a + 4 * j, x[j]);
    atomicAdd(g_cnt + d, 1.f);
}

// ---------------- SAGE layer 1: 12 -> 64 + LN + relu, fused proj h@Wn2 -------
__global__ __launch_bounds__(256) void sage1_kernel(const float* __restrict__ nf,
                                                    const float* __restrict__ Ws,
                                                    const float* __restrict__ Wn,
                                                    const float* __restrict__ b,
                                                    const float* __restrict__ g,
                                                    const float* __restrict__ be,
                                                    const float* __restrict__ Wn2) {
    __shared__ float sWs[IN_DIM * HID], sWn[IN_DIM * HID], sW2[HID * EMB];
    __shared__ float sb[HID], sg[HID], sbe[HID];
    for (int i = threadIdx.x; i < IN_DIM * HID; i += 256) { sWs[i] = Ws[i]; sWn[i] = Wn[i]; }
    for (int i = threadIdx.x; i < HID * EMB; i += 256) sW2[i] = Wn2[i];
    if (threadIdx.x < HID) {
        sb[threadIdx.x] = b[threadIdx.x];
        sg[threadIdx.x] = g[threadIdx.x];
        sbe[threadIdx.x] = be[threadIdx.x];
    }
    __syncthreads();
    int n = blockIdx.x * 8 + (threadIdx.x >> 5);
    int lane = threadIdx.x & 31;
    float inv = 1.f / fmaxf(g_cnt[n], 1.f);
    float h0 = sb[lane], h1 = sb[lane + 32];
#pragma unroll
    for (int k = 0; k < IN_DIM; k++) {
        float xk = nf[n * IN_DIM + k];
        float ak = g_agg1[n * IN_DIM + k] * inv;
        h0 += xk * sWs[k * HID + lane]      + ak * sWn[k * HID + lane];
        h1 += xk * sWs[k * HID + lane + 32] + ak * sWn[k * HID + lane + 32];
    }
    // self-clean agg1 (g_cnt still needed by sage2; sage2 zeroes it)
    __syncwarp();
    if (lane < IN_DIM) g_agg1[n * IN_DIM + lane] = 0.f;

    float s1 = warp_sum(h0 + h1);
    float s2 = warp_sum(h0 * h0 + h1 * h1);
    float mu  = s1 * (1.f / 64.f);
    float var = s2 * (1.f / 64.f) - mu * mu;
    float r = rsqrtf(var + 1e-5f);
    float o0 = fmaxf((h0 - mu) * r * sg[lane]      + sbe[lane],      0.f);
    float o1 = fmaxf((h1 - mu) * r * sg[lane + 32] + sbe[lane + 32], 0.f);
    g_h[n * HID + lane]      = o0;
    g_h[n * HID + lane + 32] = o1;
    // fused projection: p = h @ Wn2 (h is lane-distributed in o0/o1)
    float acc = 0.f;
#pragma unroll
    for (int k = 0; k < 32; k++)
        acc += __shfl_sync(0xffffffffu, o0, k) * sW2[k * EMB + lane];
#pragma unroll
    for (int k = 0; k < 32; k++)
        acc += __shfl_sync(0xffffffffu, o1, k) * sW2[(k + 32) * EMB + lane];
    g_p[n * EMB + lane] = acc;
}

// ---------------- scatter layer-2 (projected): p[src] -> agg2p[dst] ----------
__global__ __launch_bounds__(256) void scatter2_kernel(const void* __restrict__ ei) {
    int e = blockIdx.x * 256 + threadIdx.x;
    if (e >= E_MSG) return;
    bool is64 = idx_is64(ei);
    long long s = ld_idx(ei, e, is64);
    long long d = ld_idx(ei, (long long)E_MSG + e, is64);
    const float4* ps = (const float4*)(g_p + s * EMB);    // 128B rows
    float* pd = g_agg2p + d * EMB;
#pragma unroll
    for (int j = 0; j < 8; j++) red_add_v4(pd + 4 * j, ps[j]);
}

// ---------------- SAGE layer 2: 64 -> 32 + LN + relu -------------------------
__global__ __launch_bounds__(256) void sage2_kernel(const float* __restrict__ Ws,
                                                    const float* __restrict__ b,
                                                    const float* __restrict__ g,
                                                    const float* __restrict__ be) {
    __shared__ float sWs[HID * EMB];
    __shared__ float sb[EMB], sg[EMB], sbe[EMB];
    for (int i = threadIdx.x; i < HID * EMB; i += 256) sWs[i] = Ws[i];
    if (threadIdx.x < EMB) {
        sb[threadIdx.x] = b[threadIdx.x];
        sg[threadIdx.x] = g[threadIdx.x];
        sbe[threadIdx.x] = be[threadIdx.x];
    }
    __syncthreads();
    int n = blockIdx.x * 8 + (threadIdx.x >> 5);
    int lane = threadIdx.x & 31;
    float inv = 1.f / fmaxf(g_cnt[n], 1.f);
    float hl = g_h[n * HID + lane];
    float hh = g_h[n * HID + 32 + lane];
    float acc = sb[lane] + g_agg2p[n * EMB + lane] * inv;
    // self-clean agg2p and cnt AFTER all reads within this warp
    __syncwarp();
    g_agg2p[n * EMB + lane] = 0.f;
    if (lane == 0) g_cnt[n] = 0.f;
#pragma unroll
    for (int k = 0; k < 32; k++)
        acc += __shfl_sync(0xffffffffu, hl, k) * sWs[k * EMB + lane];
#pragma unroll
    for (int k = 0; k < 32; k++)
        acc += __shfl_sync(0xffffffffu, hh, k) * sWs[(k + 32) * EMB + lane];
    float s1 = warp_sum(acc);
    float s2 = warp_sum(acc * acc);
    float mu  = s1 * (1.f / 32.f);
    float var = s2 * (1.f / 32.f) - mu * mu;
    float r = rsqrtf(var + 1e-5f);
    g_emb[n * EMB + lane] = fmaxf((acc - mu) * r * sg[lane] + sbe[lane], 0.f);
}

// ---------------- fused edge_rep + edge MLP (packed f32x2) -------------------
// Shared layout (floats): W1(74*64) W2(64*32) D1(32*64) D2(64*76) b1(64) b2(32) b3(64) b4(76)
#define SM_W1 0
#define SM_W2 (SM_W1 + EDGE_REPR * HID)
#define SM_D1 (SM_W2 + HID * EMB)
#define SM_D2 (SM_D1 + EMB * HID)
#define SM_B1 (SM_D2 + HID * D2PAD)
#define SM_B2 (SM_B1 + HID)
#define SM_B3 (SM_B2 + EMB)
#define SM_B4 (SM_B3 + HID)
#define SM_TOTAL (SM_B4 + D2PAD)   // 13932 floats = 55728 B

#define MLP_THREADS 128

__global__ __launch_bounds__(MLP_THREADS, 3) void edge_mlp_kernel(
    const void* __restrict__ srcn, const void* __restrict__ dstn,
    const float* __restrict__ ea,
    const float* __restrict__ eW1, const float* __restrict__ eb1,
    const float* __restrict__ eW2, const float* __restrict__ eb2,
    const float* __restrict__ dW1, const float* __restrict__ db1,
    const float* __restrict__ dW2, const float* __restrict__ db2,
    float* __restrict__ out_recon, float* __restrict__ out_er) {
    extern __shared__ float sm[];
    for (int i = threadIdx.x; i < EDGE_REPR * HID; i += MLP_THREADS) sm[SM_W1 + i] = eW1[i];
    for (int i = threadIdx.x; i < HID * EMB; i += MLP_THREADS)       sm[SM_W2 + i] = eW2[i];
    for (int i = threadIdx.x; i < EMB * HID; i += MLP_THREADS)       sm[SM_D1 + i] = dW1[i];
    for (int i = threadIdx.x; i < HID * D2PAD; i += MLP_THREADS) {
        int k = i / D2PAD, j = i - k * D2PAD;
        sm[SM_D2 + i] = (j < EDGE_REPR) ? dW2[k * EDGE_REPR + j] : 0.f;
    }
    for (int i = threadIdx.x; i < HID; i += MLP_THREADS) { sm[SM_B1 + i] = eb1[i]; sm[SM_B3 + i] = db1[i]; }
    for (int i = threadIdx.x; i < EMB; i += MLP_THREADS)   sm[SM_B2 + i] = eb2[i];
    for (int i = threadIdx.x; i < D2PAD; i += MLP_THREADS) sm[SM_B4 + i] = (i < EDGE_REPR) ? db2[i] : 0.f;
    __syncthreads();

    int e = blockIdx.x * MLP_THREADS + threadIdx.x;
    if (e >= E_SC) return;
    bool is64s = idx_is64(srcn);
    bool is64d = idx_is64(dstn);
    long long s = ld_idx(srcn, e, is64s);
    long long d = ld_idx(dstn, e, is64d);

    // -------- gather edge representation --------
    float er[EDGE_REPR];
    {
        const float4* es = (const float4*)(g_emb + s * EMB);
        const float4* ed = (const float4*)(g_emb + d * EMB);
#pragma unroll
        for (int j = 0; j < 8; j++) {
            float4 v = es[j];
            er[4 * j] = v.x; er[4 * j + 1] = v.y; er[4 * j + 2] = v.z; er[4 * j + 3] = v.w;
        }
#pragma unroll
        for (int j = 0; j < 8; j++) {
            float4 v = ed[j];
            er[EMB + 4 * j] = v.x; er[EMB + 4 * j + 1] = v.y;
            er[EMB + 4 * j + 2] = v.z; er[EMB + 4 * j + 3] = v.w;
        }
#pragma unroll
        for (int i = 0; i < EDGE_F; i++) er[2 * EMB + i] = ea[(long long)e * EDGE_F + i];
    }
    // write edge_rep output (8B aligned: e*74*4 % 8 == 0)
    {
        unsigned long long* o = (unsigned long long*)(out_er + (long long)e * EDGE_REPR);
#pragma unroll
        for (int j = 0; j < EDGE_REPR / 2; j++) o[j] = pk2(er[2 * j], er[2 * j + 1]);
    }

    // -------- enc1: 74 -> 64, relu (packed pairs over output dim) --------
    unsigned long long a1[HID / 2];
    {
        const unsigned long long* bp = (const unsigned long long*)(sm + SM_B1);
#pragma unroll
        for (int j = 0; j < HID / 2; j++) a1[j] = bp[j];
#pragma unroll
        for (int k = 0; k < EDGE_REPR; k++) {
            unsigned long long ek = pk2(er[k], er[k]);
            const ulonglong2* w = (const ulonglong2*)(sm + SM_W1 + k * HID);
#pragma unroll
            for (int j = 0; j < HID / 4; j++) {
                ulonglong2 t = w[j];
                fma2(a1[2 * j], ek, t.x);
                fma2(a1[2 * j + 1], ek, t.y);
            }
        }
    }
    float r1[HID];
#pragma unroll
    for (int j = 0; j < HID / 2; j++) upk2(a1[j], r1[2 * j], r1[2 * j + 1]);
#pragma unroll
    for (int j = 0; j < HID; j++) r1[j] = fmaxf(r1[j], 0.f);

    // -------- enc2: 64 -> 32, relu --------
    unsigned long long a2[EMB / 2];
    {
        const unsigned long long* bp = (const unsigned long long*)(sm + SM_B2);
#pragma unroll
        for (int j = 0; j < EMB / 2; j++) a2[j] = bp[j];
#pragma unroll
        for (int k = 0; k < HID; k++) {
            unsigned long long rk = pk2(r1[k], r1[k]);
            const ulonglong2* w = (const ulonglong2*)(sm + SM_W2 + k * EMB);
#pragma unroll
            for (int j = 0; j < EMB / 4; j++) {
                ulonglong2 t = w[j];
                fma2(a2[2 * j], rk, t.x);
                fma2(a2[2 * j + 1], rk, t.y);
            }
        }
    }
    float lat[EMB];
#pragma unroll
    for (int j = 0; j < EMB / 2; j++) upk2(a2[j], lat[2 * j], lat[2 * j + 1]);
#pragma unroll
    for (int j = 0; j < EMB; j++) lat[j] = fmaxf(lat[j], 0.f);

    // -------- dec1: 32 -> 64, relu --------
    unsigned long long a3[HID / 2];
    {
        const unsigned long long* bp = (const unsigned long long*)(sm + SM_B3);
#pragma unroll
        for (int j = 0; j < HID / 2; j++) a3[j] = bp[j];
#pragma unroll
        for (int k = 0; k < EMB; k++) {
            unsigned long long lk = pk2(lat[k], lat[k]);
            const ulonglong2* w = (const ulonglong2*)(sm + SM_D1 + k * HID);
#pragma unroll
            for (int j = 0; j < HID / 4; j++) {
                ulonglong2 t = w[j];
                fma2(a3[2 * j], lk, t.x);
                fma2(a3[2 * j + 1], lk, t.y);
            }
        }
    }
    float h2[HID];
#pragma unroll
    for (int j = 0; j < HID / 2; j++) upk2(a3[j], h2[2 * j], h2[2 * j + 1]);
#pragma unroll
    for (int j = 0; j < HID; j++) h2[j] = fmaxf(h2[j], 0.f);

    // -------- dec2: 64 -> 74 (padded 76), no relu --------
    unsigned long long a4[D2PAD / 2];
    {
        const unsigned long long* bp = (const unsigned long long*)(sm + SM_B4);
#pragma unroll
        for (int j = 0; j < D2PAD / 2; j++) a4[j] = bp[j];
#pragma unroll
        for (int k = 0; k < HID; k++) {
            unsigned long long hk = pk2(h2[k], h2[k]);
            const ulonglong2* w = (const ulonglong2*)(sm + SM_D2 + k * D2PAD);
#pragma unroll
            for (int j = 0; j < D2PAD / 4; j++) {
                ulonglong2 t = w[j];
                fma2(a4[2 * j], hk, t.x);
                fma2(a4[2 * j + 1], hk, t.y);
            }
        }
    }
    {
        unsigned long long* o = (unsigned long long*)(out_recon + (long long)e * EDGE_REPR);
#pragma unroll
        for (int j = 0; j < EDGE_REPR / 2; j++) o[j] = a4[j];  // pairs 0..36 = cols 0..73
    }
}

// ---------------- launcher ----------------------------------------------------
extern "C" void kernel_launch(void* const* d_in, const int* in_sizes, int n_in,
                              void* d_out, int out_size) {
    const float* nf   = (const float*)d_in[0];
    const void*  ei   = d_in[1];
    const float* ea   = (const float*)d_in[2];
    const void*  srcn = d_in[3];
    const void*  dstn = d_in[4];
    const float* Ws1 = (const float*)d_in[5];
    const float* Wn1 = (const float*)d_in[6];
    const float* b1  = (const float*)d_in[7];
    const float* g1  = (const float*)d_in[8];
    const float* be1 = (const float*)d_in[9];
    const float* Ws2 = (const float*)d_in[10];
    const float* Wn2 = (const float*)d_in[11];
    const float* b2  = (const float*)d_in[12];
    const float* g2  = (const float*)d_in[13];
    const float* be2 = (const float*)d_in[14];
    const float* eW1 = (const float*)d_in[15];
    const float* eb1 = (const float*)d_in[16];
    const float* eW2 = (const float*)d_in[17];
    const float* eb2 = (const float*)d_in[18];
    const float* dW1 = (const float*)d_in[19];
    const float* db1 = (const float*)d_in[20];
    const float* dW2 = (const float*)d_in[21];
    const float* db2 = (const float*)d_in[22];

    float* out_recon = (float*)d_out;                                   // [1M, 74]
    float* out_er    = (float*)d_out + (long long)E_SC * EDGE_REPR;     // [1M, 74]

    const int smem_mlp = SM_TOTAL * sizeof(float);  // 55728 B
    cudaFuncSetAttribute(edge_mlp_kernel, cudaFuncAttributeMaxDynamicSharedMemorySize, smem_mlp);

    scatter1_kernel<<<(E_MSG + 255) / 256, 256>>>(ei, nf);
    sage1_kernel<<<N_NODES / 8, 256>>>(nf, Ws1, Wn1, b1, g1, be1, Wn2);
    scatter2_kernel<<<(E_MSG + 255) / 256, 256>>>(ei);
    sage2_kernel<<<N_NODES / 8, 256>>>(Ws2, b2, g2, be2);
    edge_mlp_kernel<<<(E_SC + MLP_THREADS - 1) / MLP_THREADS, MLP_THREADS, smem_mlp>>>(
        srcn, dstn, ea, eW1, eb1, eW2, eb2, dW1, db1, dW2, db2, out_recon, out_er);
}

// round 17
// speedup vs baseline: 2.6149x; 1.7547x over previous
#include <cuda_runtime.h>
#include <cstdint>

#define N_NODES 100000
#define E_MSG   3200000
#define E_SC    1000000
#define IN_DIM  12
#define HID     64
#define EMB     32
#define EDGE_F  10
#define EDGE_REPR 74

// ---------------- scratch (static device globals; zero-init at load) ---------
__device__ float g_agg1 [N_NODES * IN_DIM];
__device__ float g_cnt  [N_NODES];
__device__ float g_h    [N_NODES * HID];
__device__ float g_p    [N_NODES * EMB];
__device__ float g_agg2p[N_NODES * EMB];
__device__ float g_emb  [N_NODES * EMB];

// ---------------- int32/int64 index handling ---------------------------------
__device__ __forceinline__ bool idx_is64(const void* p) {
    const int* q = (const int*)p;
    return (q[1] | q[3] | q[5]) == 0;
}
__device__ __forceinline__ long long ld_idx(const void* p, long long i, bool is64) {
    if (is64) return ((const long long*)p)[i];
    return (long long)((const int*)p)[i];
}

__device__ __forceinline__ float warp_sum(float v) {
#pragma unroll
    for (int o = 16; o > 0; o >>= 1) v += __shfl_xor_sync(0xffffffffu, v, o);
    return v;
}

__device__ __forceinline__ unsigned long long pk2(float a, float b) {
    unsigned long long r;
    asm("mov.b64 %0, {%1,%2};" : "=l"(r) : "f"(a), "f"(b));
    return r;
}

__device__ __forceinline__ void red_add_v4(float* addr, float4 v) {
    asm volatile("red.global.add.v4.f32 [%0], {%1,%2,%3,%4};"
                 :: "l"(addr), "f"(v.x), "f"(v.y), "f"(v.z), "f"(v.w) : "memory");
}

// ================= graph stages (proven R14 versions) ========================
__global__ __launch_bounds__(256) void scatter1_kernel(const void* __restrict__ ei,
                                                       const float* __restrict__ nf) {
    int e = blockIdx.x * 256 + threadIdx.x;
    if (e >= E_MSG) return;
    bool is64 = idx_is64(ei);
    long long s = ld_idx(ei, e, is64);
    long long d = ld_idx(ei, (long long)E_MSG + e, is64);
    const float4* x = (const float4*)(nf + s * IN_DIM);
    float* a = g_agg1 + d * IN_DIM;
#pragma unroll
    for (int j = 0; j < 3; j++) red_add_v4(a + 4 * j, x[j]);
    atomicAdd(g_cnt + d, 1.f);
}

__global__ __launch_bounds__(256) void sage1_kernel(const float* __restrict__ nf,
                                                    const float* __restrict__ Ws,
                                                    const float* __restrict__ Wn,
                                                    const float* __restrict__ b,
                                                    const float* __restrict__ g,
                                                    const float* __restrict__ be,
                                                    const float* __restrict__ Wn2) {
    __shared__ float sWs[IN_DIM * HID], sWn[IN_DIM * HID], sW2[HID * EMB];
    __shared__ float sb[HID], sg[HID], sbe[HID];
    for (int i = threadIdx.x; i < IN_DIM * HID; i += 256) { sWs[i] = Ws[i]; sWn[i] = Wn[i]; }
    for (int i = threadIdx.x; i < HID * EMB; i += 256) sW2[i] = Wn2[i];
    if (threadIdx.x < HID) {
        sb[threadIdx.x] = b[threadIdx.x];
        sg[threadIdx.x] = g[threadIdx.x];
        sbe[threadIdx.x] = be[threadIdx.x];
    }
    __syncthreads();
    int n = blockIdx.x * 8 + (threadIdx.x >> 5);
    int lane = threadIdx.x & 31;
    float inv = 1.f / fmaxf(g_cnt[n], 1.f);
    float h0 = sb[lane], h1 = sb[lane + 32];
#pragma unroll
    for (int k = 0; k < IN_DIM; k++) {
        float xk = nf[n * IN_DIM + k];
        float ak = g_agg1[n * IN_DIM + k] * inv;
        h0 += xk * sWs[k * HID + lane]      + ak * sWn[k * HID + lane];
        h1 += xk * sWs[k * HID + lane + 32] + ak * sWn[k * HID + lane + 32];
    }
    __syncwarp();
    if (lane < IN_DIM) g_agg1[n * IN_DIM + lane] = 0.f;

    float s1 = warp_sum(h0 + h1);
    float s2 = warp_sum(h0 * h0 + h1 * h1);
    float mu  = s1 * (1.f / 64.f);
    float var = s2 * (1.f / 64.f) - mu * mu;
    float r = rsqrtf(var + 1e-5f);
    float o0 = fmaxf((h0 - mu) * r * sg[lane]      + sbe[lane],      0.f);
    float o1 = fmaxf((h1 - mu) * r * sg[lane + 32] + sbe[lane + 32], 0.f);
    g_h[n * HID + lane]      = o0;
    g_h[n * HID + lane + 32] = o1;
    float acc = 0.f;
#pragma unroll
    for (int k = 0; k < 32; k++)
        acc += __shfl_sync(0xffffffffu, o0, k) * sW2[k * EMB + lane];
#pragma unroll
    for (int k = 0; k < 32; k++)
        acc += __shfl_sync(0xffffffffu, o1, k) * sW2[(k + 32) * EMB + lane];
    g_p[n * EMB + lane] = acc;
}

__global__ __launch_bounds__(256) void scatter2_kernel(const void* __restrict__ ei) {
    int e = blockIdx.x * 256 + threadIdx.x;
    if (e >= E_MSG) return;
    bool is64 = idx_is64(ei);
    long long s = ld_idx(ei, e, is64);
    long long d = ld_idx(ei, (long long)E_MSG + e, is64);
    const float4* ps = (const float4*)(g_p + s * EMB);
    float* pd = g_agg2p + d * EMB;
#pragma unroll
    for (int j = 0; j < 8; j++) red_add_v4(pd + 4 * j, ps[j]);
}

__global__ __launch_bounds__(256) void sage2_kernel(const float* __restrict__ Ws,
                                                    const float* __restrict__ b,
                                                    const float* __restrict__ g,
                                                    const float* __restrict__ be) {
    __shared__ float sWs[HID * EMB];
    __shared__ float sb[EMB], sg[EMB], sbe[EMB];
    for (int i = threadIdx.x; i < HID * EMB; i += 256) sWs[i] = Ws[i];
    if (threadIdx.x < EMB) {
        sb[threadIdx.x] = b[threadIdx.x];
        sg[threadIdx.x] = g[threadIdx.x];
        sbe[threadIdx.x] = be[threadIdx.x];
    }
    __syncthreads();
    int n = blockIdx.x * 8 + (threadIdx.x >> 5);
    int lane = threadIdx.x & 31;
    float inv = 1.f / fmaxf(g_cnt[n], 1.f);
    float hl = g_h[n * HID + lane];
    float hh = g_h[n * HID + 32 + lane];
    float acc = sb[lane] + g_agg2p[n * EMB + lane] * inv;
    __syncwarp();
    g_agg2p[n * EMB + lane] = 0.f;
    if (lane == 0) g_cnt[n] = 0.f;
#pragma unroll
    for (int k = 0; k < 32; k++)
        acc += __shfl_sync(0xffffffffu, hl, k) * sWs[k * EMB + lane];
#pragma unroll
    for (int k = 0; k < 32; k++)
        acc += __shfl_sync(0xffffffffu, hh, k) * sWs[(k + 32) * EMB + lane];
    float s1 = warp_sum(acc);
    float s2 = warp_sum(acc * acc);
    float mu  = s1 * (1.f / 32.f);
    float var = s2 * (1.f / 32.f) - mu * mu;
    float r = rsqrtf(var + 1e-5f);
    g_emb[n * EMB + lane] = fmaxf((acc - mu) * r * sg[lane] + sbe[lane], 0.f);
}

// ================= HMMA edge MLP (mma.sync m16n8k16 bf16, hi/lo split) =======
// Each warp processes 16 edges independently. Outputs repack to next-layer A
// fragments entirely in registers (C layout of 2 adjacent N-tiles == A layout).
// Biases folded as an extra K column with A=1.

#define NTILES_MLP ((E_SC + 127) / 128)     // 7813 (128 edges per block-tile)
#define STAGE_STRIDE 84                     // floats per staged edge row (conflict-free)

// byte offsets in dynamic smem
#define OFF_STAGE 0u
#define OFF_B1H   43008u   /* 64 x 88 bf16 */
#define OFF_B1L   54272u
#define OFF_B2H   65536u   /* 32 x 88 */
#define OFF_B2L   71168u
#define OFF_B3H   76800u   /* 64 x 56 */
#define OFF_B3L   83968u
#define OFF_B4H   91136u   /* 80 x 88 */
#define OFF_B4L   105216u
#define SMEM_DYN  119296u
#define WEIGHT_BYTES (SMEM_DYN - OFF_B1H)

// pack two fp32 into bf16x2: lower half = `even`, upper = `odd`
__device__ __forceinline__ uint32_t pack_bf16(float even, float odd) {
    uint32_t r;
    asm("cvt.rn.bf16x2.f32 %0, %1, %2;" : "=r"(r) : "f"(odd), "f"(even));
    return r;
}
__device__ __forceinline__ void split2(float e, float o, uint32_t& hi, uint32_t& lo) {
    hi = pack_bf16(e, o);
    float eh = __uint_as_float(hi << 16);
    float oh = __uint_as_float(hi & 0xFFFF0000u);
    lo = pack_bf16(e - eh, o - oh);
}
__device__ __forceinline__ void mma_bf16(float* c, uint32_t a0, uint32_t a1,
                                         uint32_t a2, uint32_t a3,
                                         uint32_t b0, uint32_t b1) {
    asm("mma.sync.aligned.m16n8k16.row.col.f32.bf16.bf16.f32 "
        "{%0,%1,%2,%3},{%4,%5,%6,%7},{%8,%9},{%0,%1,%2,%3};"
        : "+f"(c[0]), "+f"(c[1]), "+f"(c[2]), "+f"(c[3])
        : "r"(a0), "r"(a1), "r"(a2), "r"(a3), "r"(b0), "r"(b1));
}

// run one GEMM layer: C[M16 x 8*NT] += A[16 x 16*KS] * B^T  (3 hi/lo products)
template<int KS, int NT, int STRIDE>
__device__ __forceinline__ void run_layer(const char* bH, const char* bL,
                                          const uint32_t* aH, const uint32_t* aL,
                                          float* C, int g, int t) {
#pragma unroll
    for (int j = 0; j < KS; j++) {
#pragma unroll
        for (int m = 0; m < NT; m++) {
            int base = ((8 * m + g) * STRIDE + 16 * j + 2 * t) * 2;
            uint32_t bh0 = *(const uint32_t*)(bH + base);
            uint32_t bh1 = *(const uint32_t*)(bH + base + 16);
            uint32_t bl0 = *(const uint32_t*)(bL + base);
            uint32_t bl1 = *(const uint32_t*)(bL + base + 16);
            mma_bf16(C + 4 * m, aH[4 * j], aH[4 * j + 1], aH[4 * j + 2], aH[4 * j + 3], bh0, bh1);
            mma_bf16(C + 4 * m, aH[4 * j], aH[4 * j + 1], aH[4 * j + 2], aH[4 * j + 3], bl0, bl1);
            mma_bf16(C + 4 * m, aL[4 * j], aL[4 * j + 1], aL[4 * j + 2], aL[4 * j + 3], bh0, bh1);
        }
    }
}

// repack C (NT tiles) with relu into A fragments for next layer (NT/2 ksteps)
template<int NT>
__device__ __forceinline__ void repack_relu(const float* C, uint32_t* aH, uint32_t* aL) {
#pragma unroll
    for (int j2 = 0; j2 < NT / 2; j2++) {
        const float* c0 = C + 8 * j2;
        const float* c1 = C + 8 * j2 + 4;
        split2(fmaxf(c0[0], 0.f), fmaxf(c0[1], 0.f), aH[4 * j2],     aL[4 * j2]);
        split2(fmaxf(c0[2], 0.f), fmaxf(c0[3], 0.f), aH[4 * j2 + 1], aL[4 * j2 + 1]);
        split2(fmaxf(c1[0], 0.f), fmaxf(c1[1], 0.f), aH[4 * j2 + 2], aL[4 * j2 + 2]);
        split2(fmaxf(c1[2], 0.f), fmaxf(c1[3], 0.f), aH[4 * j2 + 3], aL[4 * j2 + 3]);
    }
}
__device__ __forceinline__ void set_bias_frag(uint32_t* aH, uint32_t* aL, int j, int t) {
    uint32_t one = (t == 0) ? 0x00003F80u : 0u;   // bf16(1.0) at even col 0
    aH[4 * j] = one; aH[4 * j + 1] = one; aH[4 * j + 2] = 0u; aH[4 * j + 3] = 0u;
    aL[4 * j] = 0u; aL[4 * j + 1] = 0u; aL[4 * j + 2] = 0u; aL[4 * j + 3] = 0u;
}

// stage W[K][N] (+bias as col K) transposed into bf16 hi/lo smem tiles
__device__ void stage_B(char* dH, char* dL, const float* __restrict__ W,
                        const float* __restrict__ bias, int K, int N, int stride, int tid) {
    for (int i = tid; i < K * N; i += 256) {
        int k = i / N, n = i - k * N;
        float x = W[i];
        uint32_t h = pack_bf16(x, 0.f);
        float hf = __uint_as_float(h << 16);
        uint32_t l = pack_bf16(x - hf, 0.f);
        int o = (n * stride + k) * 2;
        *(unsigned short*)(dH + o) = (unsigned short)(h & 0xffffu);
        *(unsigned short*)(dL + o) = (unsigned short)(l & 0xffffu);
    }
    for (int n = tid; n < N; n += 256) {
        float x = bias[n];
        uint32_t h = pack_bf16(x, 0.f);
        float hf = __uint_as_float(h << 16);
        uint32_t l = pack_bf16(x - hf, 0.f);
        int o = (n * stride + K) * 2;
        *(unsigned short*)(dH + o) = (unsigned short)(h & 0xffffu);
        *(unsigned short*)(dL + o) = (unsigned short)(l & 0xffffu);
    }
}

__global__ __launch_bounds__(256, 1) void edge_mlp_hmma(
    const void* __restrict__ srcn, const void* __restrict__ dstn,
    const float* __restrict__ ea,
    const float* __restrict__ eW1, const float* __restrict__ eb1,
    const float* __restrict__ eW2, const float* __restrict__ eb2,
    const float* __restrict__ dW1, const float* __restrict__ db1,
    const float* __restrict__ dW2, const float* __restrict__ db2,
    float* __restrict__ out_recon, float* __restrict__ out_er) {
    extern __shared__ char dyn[];
    float* stag = (float*)(dyn + OFF_STAGE);
    char* B1H = dyn + OFF_B1H; char* B1L = dyn + OFF_B1L;
    char* B2H = dyn + OFF_B2H; char* B2L = dyn + OFF_B2L;
    char* B3H = dyn + OFF_B3H; char* B3L = dyn + OFF_B3L;
    char* B4H = dyn + OFF_B4H; char* B4L = dyn + OFF_B4L;

    int tid = threadIdx.x;
    int w = tid >> 5, lane = tid & 31;
    int g = lane >> 2, t = lane & 3;

    // zero weight region, then stage all four weight matrices (hi/lo, transposed)
    for (uint32_t i = (uint32_t)tid * 8u; i < WEIGHT_BYTES; i += 256u * 8u)
        *(unsigned long long*)(dyn + OFF_B1H + i) = 0ull;
    __syncthreads();
    stage_B(B1H, B1L, eW1, eb1, 74, 64, 88, tid);
    stage_B(B2H, B2L, eW2, eb2, 64, 32, 88, tid);
    stage_B(B3H, B3L, dW1, db1, 32, 64, 56, tid);
    stage_B(B4H, B4L, dW2, db2, 64, 74, 88, tid);
    __syncthreads();

    bool is64s = idx_is64(srcn);
    bool is64d = idx_is64(dstn);

    for (int tile = blockIdx.x; tile < NTILES_MLP; tile += gridDim.x) {
        long long e0 = (long long)tile * 128 + w * 16;
        __syncwarp();

        // -------- gather: 2 lanes per edge fill staging row [84 floats] ------
        {
            int r = lane >> 1;
            int half = lane & 1;
            long long e = e0 + r;
            bool act = e < E_SC;
            float* row = stag + (w * 16 + r) * STAGE_STRIDE;
            if (half == 0) {
                if (act) {
                    long long s = ld_idx(srcn, e, is64s);
                    const float4* p = (const float4*)(g_emb + s * EMB);
#pragma unroll
                    for (int j = 0; j < 8; j++) ((float4*)row)[j] = p[j];
#pragma unroll
                    for (int q = 0; q < 5; q++) row[64 + q] = ea[e * EDGE_F + q];
                } else {
#pragma unroll
                    for (int j = 0; j < 8; j++) ((float4*)row)[j] = make_float4(0, 0, 0, 0);
#pragma unroll
                    for (int q = 0; q < 5; q++) row[64 + q] = 0.f;
                }
            } else {
                if (act) {
                    long long d = ld_idx(dstn, e, is64d);
                    const float4* p = (const float4*)(g_emb + d * EMB);
#pragma unroll
                    for (int j = 0; j < 8; j++) ((float4*)(row + 32))[j] = p[j];
#pragma unroll
                    for (int q = 0; q < 5; q++) row[69 + q] = ea[e * EDGE_F + 5 + q];
                } else {
#pragma unroll
                    for (int j = 0; j < 8; j++) ((float4*)(row + 32))[j] = make_float4(0, 0, 0, 0);
#pragma unroll
                    for (int q = 0; q < 5; q++) row[69 + q] = 0.f;
                }
                row[74] = 1.f;
#pragma unroll
                for (int q = 75; q < 80; q++) row[q] = 0.f;
            }
        }
        __syncwarp();

        // -------- write out_er (coalesced from staging) --------
        for (int r = 0; r < 16; r++) {
            long long e = e0 + r;
            if (e >= E_SC) break;
            const float* row = stag + (w * 16 + r) * STAGE_STRIDE;
            float* o = out_er + e * EDGE_REPR;
            for (int c = lane; c < EDGE_REPR; c += 32) o[c] = row[c];
        }

        // -------- enc1 A fragments from staging --------
        uint32_t aH[20], aL[20];
        {
            const float* r0 = stag + (w * 16 + g) * STAGE_STRIDE;
            const float* r1 = stag + (w * 16 + g + 8) * STAGE_STRIDE;
#pragma unroll
            for (int j = 0; j < 5; j++) {
                float2 v;
                v = *(const float2*)(r0 + 16 * j + 2 * t);      split2(v.x, v.y, aH[4 * j],     aL[4 * j]);
                v = *(const float2*)(r1 + 16 * j + 2 * t);      split2(v.x, v.y, aH[4 * j + 1], aL[4 * j + 1]);
                v = *(const float2*)(r0 + 16 * j + 8 + 2 * t);  split2(v.x, v.y, aH[4 * j + 2], aL[4 * j + 2]);
                v = *(const float2*)(r1 + 16 * j + 8 + 2 * t);  split2(v.x, v.y, aH[4 * j + 3], aL[4 * j + 3]);
            }
        }

        // -------- enc1: K 5 steps, N 8 tiles --------
        float C1[32];
#pragma unroll
        for (int i = 0; i < 32; i++) C1[i] = 0.f;
        run_layer<5, 8, 88>(B1H, B1L, aH, aL, C1, g, t);

        // -------- enc2: relu(C1) -> A (4 ksteps) + bias kstep4; N 4 tiles ----
        repack_relu<8>(C1, aH, aL);
        set_bias_frag(aH, aL, 4, t);
        float C2[16];
#pragma unroll
        for (int i = 0; i < 16; i++) C2[i] = 0.f;
        run_layer<5, 4, 88>(B2H, B2L, aH, aL, C2, g, t);

        // -------- dec1: relu(C2) -> A (2 ksteps) + bias kstep2; N 8 tiles ----
        repack_relu<4>(C2, aH, aL);
        set_bias_frag(aH, aL, 2, t);
        float C3[32];
#pragma unroll
        for (int i = 0; i < 32; i++) C3[i] = 0.f;
        run_layer<3, 8, 56>(B3H, B3L, aH, aL, C3, g, t);

        // -------- dec2: relu(C3) -> A (4 ksteps) + bias kstep4; N 10 tiles ---
        repack_relu<8>(C3, aH, aL);
        set_bias_frag(aH, aL, 4, t);
        float C4[40];
#pragma unroll
        for (int i = 0; i < 40; i++) C4[i] = 0.f;
        run_layer<5, 10, 88>(B4H, B4L, aH, aL, C4, g, t);

        // -------- store recon --------
        {
            bool actg  = (e0 + g) < E_SC;
            bool actg8 = (e0 + g + 8) < E_SC;
            float* o0 = out_recon + (e0 + g) * EDGE_REPR;
            float* o1 = out_recon + (e0 + g + 8) * EDGE_REPR;
#pragma unroll
            for (int m = 0; m < 10; m++) {
                int col = 8 * m + 2 * t;
                if (col < EDGE_REPR) {
                    if (actg)  *(unsigned long long*)(o0 + col) = pk2(C4[4 * m], C4[4 * m + 1]);
                    if (actg8) *(unsigned long long*)(o1 + col) = pk2(C4[4 * m + 2], C4[4 * m + 3]);
                }
            }
        }
    }
}

// ---------------- launcher ----------------------------------------------------
extern "C" void kernel_launch(void* const* d_in, const int* in_sizes, int n_in,
                              void* d_out, int out_size) {
    const float* nf   = (const float*)d_in[0];
    const void*  ei   = d_in[1];
    const float* ea   = (const float*)d_in[2];
    const void*  srcn = d_in[3];
    const void*  dstn = d_in[4];
    const float* Ws1 = (const float*)d_in[5];
    const float* Wn1 = (const float*)d_in[6];
    const float* b1  = (const float*)d_in[7];
    const float* g1  = (const float*)d_in[8];
    const float* be1 = (const float*)d_in[9];
    const float* Ws2 = (const float*)d_in[10];
    const float* Wn2 = (const float*)d_in[11];
    const float* b2  = (const float*)d_in[12];
    const float* g2  = (const float*)d_in[13];
    const float* be2 = (const float*)d_in[14];
    const float* eW1 = (const float*)d_in[15];
    const float* eb1 = (const float*)d_in[16];
    const float* eW2 = (const float*)d_in[17];
    const float* eb2 = (const float*)d_in[18];
    const float* dW1 = (const float*)d_in[19];
    const float* db1 = (const float*)d_in[20];
    const float* dW2 = (const float*)d_in[21];
    const float* db2 = (const float*)d_in[22];

    float* out_recon = (float*)d_out;
    float* out_er    = (float*)d_out + (long long)E_SC * EDGE_REPR;

    int sms = 148;
    cudaDeviceGetAttribute(&sms, cudaDevAttrMultiProcessorCount, 0);
    cudaFuncSetAttribute(edge_mlp_hmma, cudaFuncAttributeMaxDynamicSharedMemorySize, SMEM_DYN);

    scatter1_kernel<<<(E_MSG + 255) / 256, 256>>>(ei, nf);
    sage1_kernel<<<N_NODES / 8, 256>>>(nf, Ws1, Wn1, b1, g1, be1, Wn2);
    scatter2_kernel<<<(E_MSG + 255) / 256, 256>>>(ei);
    sage2_kernel<<<N_NODES / 8, 256>>>(Ws2, b2, g2, be2);
    edge_mlp_hmma<<<sms, 256, SMEM_DYN>>>(
        srcn, dstn, ea, eW1, eb1, eW2, eb2, dW1, db1, dW2, db2, out_recon, out_er);
}